// round 15
// baseline (speedup 1.0000x reference)
#include <cuda_runtime.h>
#include <cuda_bf16.h>
#include <cstdint>

// AddingGaussianBlur: x (64,512,512,3) f32, stds (64,) f32 -> out f32.
//
// Separable (reference's 3x3 kernel depends only on column index):
//   out = inv * sum_{3 rows} h(row),  h[e] = a*(x[e-3]+x[e+3]) + x[e]
//   a = exp(-1/s^2), s = 3*std[b], inv = 1/(3*(1+2a))
//
// R15 = R14 (horizontal-first 7-slot ring, depth-5, 5 blocks/SM, RPB=16)
// with the producer switched from 384 per-thread cp.asyncs per row to ONE
// cp.async.bulk (TMA, 6144B) per row issued by thread 0, completion via a
// per-slot mbarrier. Kills the LDGSTS issue/LSU load and its smem-write
// wavefronts (issue pipe was the binding roof at 52%).

#define H       512
#define ROWW    1536            // floats per image row
#define ROWB    6144            // bytes per image row
#define NT      384             // one thread per float4 chunk
#define RPB     16              // rows per block band
#define NSLOT   7               // ring slots -> 42KB ring

__global__ __launch_bounds__(NT)
void gauss_blur_kernel(const float* __restrict__ x,
                       const float* __restrict__ stds,
                       float* __restrict__ out)
{
    __shared__ __align__(16) float ring[NSLOT][ROWW];
    __shared__ __align__(8) uint64_t mbar[NSLOT];

    const int b  = blockIdx.y;
    const int i0 = blockIdx.x * RPB;
    const int t  = threadIdx.x;

    const float s   = stds[b] * 3.0f;
    const float a   = expf(-1.0f / (s * s));
    const float inv = 1.0f / (3.0f * (1.0f + 2.0f * a));

    const float* __restrict__ xb = x   + (size_t)b * H * ROWW;
    float*       __restrict__ ob = out + (size_t)b * H * ROWW;

    const uint32_t ring_base = (uint32_t)__cvta_generic_to_shared(&ring[0][0]);
    const uint32_t mbar_base = (uint32_t)__cvta_generic_to_shared(&mbar[0]);
    const float4 Z = make_float4(0.0f, 0.0f, 0.0f, 0.0f);
    const bool hasL = (t > 0);
    const bool hasR = (t < NT - 1);
    const int  iend = i0 + RPB;       // last row this band ever reads

    if (t == 0) {
        #pragma unroll
        for (int q = 0; q < NSLOT; q++)
            asm volatile("mbarrier.init.shared::cta.b64 [%0], 1;"
                         :: "r"(mbar_base + q * 8) : "memory");
        asm volatile("fence.proxy.async.shared::cta;" ::: "memory");
    }
    __syncthreads();

    // Producer (thread 0): one bulk-TMA per row. Invalid rows get a dummy
    // expect_tx(0) so the slot's phase still completes (parity discipline).
    // Rows past iend are never issued (and never read).
    auto issue = [&](int gi, int slot) {
        if (t == 0 && gi <= iend) {
            const uint32_t mb = mbar_base + slot * 8;
            if ((unsigned)gi < (unsigned)H) {
                const void* src = xb + (size_t)gi * ROWW;
                const uint32_t dst = ring_base + slot * ROWB;
                asm volatile(
                    "mbarrier.arrive.expect_tx.shared::cta.b64 _, [%0], %1;\n\t"
                    "cp.async.bulk.shared::cta.global.mbarrier::complete_tx::bytes "
                    "[%2], [%3], %1, [%0];"
                    :: "r"(mb), "r"(ROWB), "r"(dst), "l"(src) : "memory");
            } else {
                asm volatile(
                    "mbarrier.arrive.expect_tx.shared::cta.b64 _, [%0], 0;"
                    :: "r"(mb) : "memory");
            }
        }
    };

    // Consumer wait: try_wait parity loop with acquire.
    auto wait = [&](int slot, int phase) {
        const uint32_t mb = mbar_base + slot * 8;
        asm volatile(
            "{\n\t"
            ".reg .pred P;\n\t"
            "W_%=:\n\t"
            "mbarrier.try_wait.parity.acquire.cta.shared::cta.b64 P, [%0], %1, 0x989680;\n\t"
            "@P bra D_%=;\n\t"
            "bra W_%=;\n\t"
            "D_%=:\n\t"
            "}"
            :: "r"(mb), "r"(phase) : "memory");
    };

    // Horizontal pass on the row in `slot`: h[e] = a*(x[e-3]+x[e+3]) + x[e].
    auto hrow = [&](int slot) -> float4 {
        const float4* rp4 = reinterpret_cast<const float4*>(ring[slot]);
        const float4 C = rp4[t];
        const float4 L = hasL ? rp4[t - 1] : Z;
        const float4 R = hasR ? rp4[t + 1] : Z;
        float4 h;
        h.x = fmaf(a, L.y + C.w, C.x);
        h.y = fmaf(a, L.z + R.x, C.y);
        h.z = fmaf(a, L.w + R.y, C.z);
        h.w = fmaf(a, C.x + R.z, C.w);
        return h;
    };

    // Prologue: rows i0-1 .. i0+5 into slots 0..6; wait slots 0,1 (parity 0).
    issue(i0 - 1, 0); issue(i0,     1); issue(i0 + 1, 2); issue(i0 + 2, 3);
    issue(i0 + 3, 4); issue(i0 + 4, 5); issue(i0 + 5, 6);

    wait(0, 0);
    float4 hm = (i0 > 0) ? hrow(0) : Z;   // h(row i0-1)
    wait(1, 0);
    float4 hc = hrow(1);                  // h(row i0)

    int sl_rd = 2;   // slot of row gi+1 at iteration r   ((r+2) mod 7)
    int sl_wr = 0;   // slot for row gi+6 at iteration r  (r mod 7)
    int ph    = 0;   // read parity; flips when sl_rd wraps 6 -> 0

    #pragma unroll 1
    for (int r = 0; r < RPB; r++) {
        const int gi = i0 + r;

        // Re-arm + refill slot sl_wr (held row gi-1, last read at iter r-2;
        // all threads passed barrier r-1 since then -> WAR safe).
        issue(gi + 6, sl_wr);

        // Row gi+1's slot complete, then block-wide backpressure barrier
        // (bounds thread skew to one iteration, protecting the re-arm above).
        wait(sl_rd, ph);
        __syncthreads();

        const float4 hp = (gi + 1 < H) ? hrow(sl_rd) : Z;   // h(row gi+1)

        float4 o;
        o.x = inv * (hm.x + hc.x + hp.x);
        o.y = inv * (hm.y + hc.y + hp.y);
        o.z = inv * (hm.z + hc.z + hp.z);
        o.w = inv * (hm.w + hc.w + hp.w);

        __stcs(&reinterpret_cast<float4*>(ob + (size_t)gi * ROWW)[t], o);

        hm = hc; hc = hp;
        sl_wr = (sl_wr + 1 == NSLOT) ? 0 : sl_wr + 1;
        if (++sl_rd == NSLOT) { sl_rd = 0; ph ^= 1; }
    }
}

extern "C" void kernel_launch(void* const* d_in, const int* in_sizes, int n_in,
                              void* d_out, int out_size)
{
    const float* x    = (const float*)d_in[0];
    const float* stds = (const float*)d_in[1];
    float* out        = (float*)d_out;

    dim3 grid(H / RPB, 64);   // (32, 64) = 2048 blocks
    gauss_blur_kernel<<<grid, NT>>>(x, stds, out);
}